// round 5
// baseline (speedup 1.0000x reference)
#include <cuda_runtime.h>
#include <math.h>

#define A_N 33600
#define G_N 300
#define C_N 80
#define FINF __int_as_float(0x7f800000)

// ---------------- scratch ----------------
__device__ float g_spart[A_N * 4];
__device__ float g_sall[A_N];
__device__ unsigned char g_fg[A_N];
__device__ int   g_cnt[A_N];
__device__ int   g_mgt[A_N];
__device__ float g_miou[A_N];
__device__ int   g_multi[A_N];
__device__ int   g_mcnt;
__device__ int   g_numfg;
__device__ int   g_Di[12];                     // per-level {exp,exn,eyp,eyn} float-as-int (>=0)
__device__ int   g_fb[G_N];
__device__ int   g_dk[G_N];
__device__ unsigned long long g_fkey[G_N * 8 * 10];

__device__ __forceinline__ float f_mul(float a, float b) { return __fmul_rn(a, b); }
__device__ __forceinline__ float f_add(float a, float b) { return __fadd_rn(a, b); }
__device__ __forceinline__ float f_sub(float a, float b) { return __fadd_rn(a, -b); }

struct GTBox { float x, y, tlx, tly, brx, bry, area; };

__device__ __forceinline__ GTBox make_gt(const float* __restrict__ gt, int g) {
    GTBox B;
    float gx = gt[g * 4 + 0], gy = gt[g * 4 + 1], gw = gt[g * 4 + 2], gh = gt[g * 4 + 3];
    B.x = gx; B.y = gy;
    B.tlx = f_sub(gx, f_mul(0.5f, gw));
    B.tly = f_sub(gy, f_mul(0.5f, gh));
    B.brx = f_add(gx, f_mul(0.5f, gw));
    B.bry = f_add(gy, f_mul(0.5f, gh));
    B.area = f_mul(gw, gh);
    return B;
}

__device__ __forceinline__ float masked_iou(const GTBox& B, float4 p, bool fg) {
    float hw = f_mul(0.5f, p.z), hh = f_mul(0.5f, p.w);
    float tlx = fmaxf(B.tlx, f_sub(p.x, hw));
    float tly = fmaxf(B.tly, f_sub(p.y, hh));
    float brx = fminf(B.brx, f_add(p.x, hw));
    float bry = fminf(B.bry, f_add(p.y, hh));
    float w = fmaxf(f_sub(brx, tlx), 0.f);
    float h = fmaxf(f_sub(bry, tly), 0.f);
    float inter = f_mul(w, h);
    float uni = f_sub(f_add(B.area, f_mul(p.z, p.w)), inter);
    float iou = inter / uni;
    return fg ? iou : 0.f;
}

__device__ __forceinline__ void anchor_geom(int a, float& cx, float& cy, float& r) {
    int xi, yi; float s;
    if (a < 25600)      { yi = a / 160;          xi = a - yi * 160;          s = 8.f;  r = 20.f; }
    else if (a < 32000) { int b = a - 25600; yi = b / 80;  xi = b - yi * 80;  s = 16.f; r = 40.f; }
    else                { int b = a - 32000; yi = b / 40;  xi = b - yi * 40;  s = 32.f; r = 80.f; }
    cx = f_mul(f_add((float)xi, 0.5f), s);
    cy = f_mul(f_add((float)yi, 0.5f), s);
}

__device__ __forceinline__ bool is_cand(const GTBox& B, float cx, float cy, float r) {
    bool inb = (cx > B.tlx) && (B.brx > cx) && (cy > B.tly) && (B.bry > cy);
    bool inc = (cx > f_sub(B.x, r)) && (f_add(B.x, r) > cx) &&
               (cy > f_sub(B.y, r)) && (f_add(B.y, r) > cy);
    return inb && inc;
}

__device__ __forceinline__ unsigned long long cost_key(float c, int a) {
    unsigned u = __float_as_uint(c);
    u ^= (((int)u >> 31) | 0x80000000u);
    return ((unsigned long long)u << 32) | (unsigned)a;
}

// exact t = log(p) - log1p(-p), bit-identical to R4's accurate chain (candidates only)
__device__ __forceinline__ float t_exact(float z, float o) {
    float sz = 1.f / (1.f + expf(-z));
    float so = 1.f / (1.f + expf(-o));
    float p = sqrtf(f_mul(sz, so));
    p = fminf(fmaxf(p, 1e-7f), 1.0f - 1e-7f);
    return f_sub(logf(p), log1pf(-p));
}

// fast s_all term: w = clamp(1 - rsqrt((1+e^-z)(1+e^-o)), 1e-7, 1-1e-7)
__device__ __forceinline__ float wterm(float z, float Bo) {
    float v = __fmaf_rn(__expf(-z), Bo, Bo);    // (1+e^-z) * Bo
    float w = 1.f - rsqrtf(v);
    return fminf(fmaxf(w, 1e-7f), 1.f - 1e-7f);
}

// ---------------- K0: zero ----------------
__global__ void k_zero() {
    int i = blockIdx.x * blockDim.x + threadIdx.x;
    if (i < A_N) { g_cnt[i] = 0; g_fg[i] = 0; }
    if (i < G_N) g_fb[i] = 0;
    if (i < 12)  g_Di[i] = 0;
    if (i == 0) { g_mcnt = 0; g_numfg = 0; }
}

// ---------------- K1: s_all partials — thread per (anchor, class-quarter) ----------------
__global__ __launch_bounds__(256) void k_sall_part(
    const float* __restrict__ cls, const float* __restrict__ obj,
    const int* __restrict__ pbatch)
{
    int idx = blockIdx.x * blockDim.x + threadIdx.x;
    if (idx >= A_N * 4) return;
    int a = idx >> 2, q = idx & 3;
    long long b = (long long)(*pbatch);
    float Bo = 1.f + __expf(-obj[b * A_N + a]);
    const float4* __restrict__ row =
        (const float4*)(cls + ((long long)b * A_N + a) * C_N + q * 20);
    float prod = 1.f;
    int ecnt = 0;
#pragma unroll
    for (int k = 0; k < 5; k++) {
        float4 zv = row[k];
        prod = prod * wterm(zv.x, Bo);
        prod = prod * wterm(zv.y, Bo);
        prod = prod * wterm(zv.z, Bo);
        prod = prod * wterm(zv.w, Bo);
        unsigned bb = __float_as_uint(prod);     // prod > 0 always
        ecnt += (int)(bb >> 23) - 127;
        prod = __uint_as_float((bb & 0x007FFFFFu) | 0x3F800000u);
    }
    g_spart[idx] = __fmaf_rn((float)ecnt, 0.6931471805599453f, __logf(prod));
}

// ---------------- K2: per-level pred-box extent bounds + s_all combine ----------------
__global__ __launch_bounds__(256) void k_bounds(const float4* __restrict__ pb) {
    int a = blockIdx.x * blockDim.x + threadIdx.x;
    if (a >= A_N) return;
    g_sall[a] = f_add(f_add(f_add(g_spart[a * 4], g_spart[a * 4 + 1]),
                            g_spart[a * 4 + 2]), g_spart[a * 4 + 3]);
    float cx, cy, r;
    anchor_geom(a, cx, cy, r);
    int lvl = (a < 25600) ? 0 : (a < 32000 ? 1 : 2);
    float4 p = pb[a];
    float hw = f_mul(0.5f, p.z), hh = f_mul(0.5f, p.w);
    float exp_ = fmaxf(f_sub(f_add(p.x, hw), cx), 0.f);
    float exn  = fmaxf(f_sub(cx, f_sub(p.x, hw)), 0.f);
    float eyp  = fmaxf(f_sub(f_add(p.y, hh), cy), 0.f);
    float eyn  = fmaxf(f_sub(cy, f_sub(p.y, hh)), 0.f);
#pragma unroll
    for (int o = 16; o; o >>= 1) {
        exp_ = fmaxf(exp_, __shfl_down_sync(0xffffffffu, exp_, o));
        exn  = fmaxf(exn,  __shfl_down_sync(0xffffffffu, exn,  o));
        eyp  = fmaxf(eyp,  __shfl_down_sync(0xffffffffu, eyp,  o));
        eyn  = fmaxf(eyn,  __shfl_down_sync(0xffffffffu, eyn,  o));
    }
    if ((threadIdx.x & 31) == 0) {   // warps are level-homogeneous (boundaries %32==0)
        atomicMax(&g_Di[lvl * 4 + 0], __float_as_int(exp_));
        atomicMax(&g_Di[lvl * 4 + 1], __float_as_int(exn));
        atomicMax(&g_Di[lvl * 4 + 2], __float_as_int(eyp));
        atomicMax(&g_Di[lvl * 4 + 3], __float_as_int(eyn));
    }
}

// ---------------- K3: fg marking per gt window ----------------
__global__ __launch_bounds__(128) void k_fgmark(const float* __restrict__ gt) {
    int g = blockIdx.x;
    __shared__ GTBox sgt;
    if (threadIdx.x == 0) sgt = make_gt(gt, g);
    __syncthreads();
    GTBox B = sgt;
    const int Loff[3] = {0, 25600, 32000}, Ln[3] = {160, 80, 40};
    const float Ls[3] = {8.f, 16.f, 32.f}, Lr[3] = {20.f, 40.f, 80.f};
    for (int l = 0; l < 3; l++) {
        float s = Ls[l], r = Lr[l];
        int n = Ln[l];
        float xlo_f = fminf(B.tlx, f_sub(B.x, r)), xhi_f = fmaxf(B.brx, f_add(B.x, r));
        float ylo_f = fminf(B.tly, f_sub(B.y, r)), yhi_f = fmaxf(B.bry, f_add(B.y, r));
        int xlo = max(0, (int)floorf(xlo_f / s - 0.5f) - 1);
        int xhi = min(n - 1, (int)ceilf(xhi_f / s - 0.5f) + 1);
        int ylo = max(0, (int)floorf(ylo_f / s - 0.5f) - 1);
        int yhi = min(n - 1, (int)ceilf(yhi_f / s - 0.5f) + 1);
        if (xhi < xlo || yhi < ylo) continue;
        int W = xhi - xlo + 1, H = yhi - ylo + 1;
        for (int idx = threadIdx.x; idx < W * H; idx += 128) {
            int yi = ylo + idx / W, xi = xlo + idx % W;
            float cx = f_mul(f_add((float)xi, 0.5f), s);
            float cy = f_mul(f_add((float)yi, 0.5f), s);
            bool inb = (cx > B.tlx) && (B.brx > cx) && (cy > B.tly) && (B.bry > cy);
            bool inc = (cx > f_sub(B.x, r)) && (f_add(B.x, r) > cx) &&
                       (cy > f_sub(B.y, r)) && (f_add(B.y, r) > cy);
            if (inb || inc) g_fg[Loff[l] + yi * n + xi] = 1;
        }
    }
}

// ---------------- K4: fused windowed assignment per gt ----------------
__global__ __launch_bounds__(256) void k_assign(
    const float* __restrict__ gt, const int* __restrict__ gtc,
    const float4* __restrict__ pb,
    const float* __restrict__ cls, const float* __restrict__ obj,
    const int* __restrict__ pbatch)
{
    int g = blockIdx.x;
    __shared__ GTBox sgt; __shared__ int scls;
    __shared__ float sV[2560];
    __shared__ unsigned long long sKey[96];
    __shared__ float sCiou[96];
    __shared__ int sCnt, sDk;
    if (threadIdx.x == 0) { sgt = make_gt(gt, g); scls = gtc[g]; sCnt = 0; }
    __syncthreads();
    GTBox B = sgt;
    long long b = (long long)(*pbatch);
    const int Loff[3] = {0, 25600, 32000}, Ln[3] = {160, 80, 40};
    const float Ls[3] = {8.f, 16.f, 32.f}, Lr[3] = {20.f, 40.f, 80.f};
    float lvv[10];
#pragma unroll
    for (int k = 0; k < 10; k++) lvv[k] = 0.f;

    for (int l = 0; l < 3; l++) {
        float s = Ls[l], r = Lr[l];
        int n = Ln[l];
        float Dxp = f_add(__int_as_float(g_Di[l * 4 + 0]), 1.0f);
        float Dxn = f_add(__int_as_float(g_Di[l * 4 + 1]), 1.0f);
        float Dyp = f_add(__int_as_float(g_Di[l * 4 + 2]), 1.0f);
        float Dyn = f_add(__int_as_float(g_Di[l * 4 + 3]), 1.0f);
        int xlo = max(0, (int)floorf((B.tlx - Dxp) / s - 0.5f) - 1);
        int xhi = min(n - 1, (int)ceilf((B.brx + Dxn) / s - 0.5f) + 1);
        int ylo = max(0, (int)floorf((B.tly - Dyp) / s - 0.5f) - 1);
        int yhi = min(n - 1, (int)ceilf((B.bry + Dyn) / s - 0.5f) + 1);
        if (xhi < xlo || yhi < ylo) continue;
        int W = xhi - xlo + 1, H = yhi - ylo + 1;
        for (int idx = threadIdx.x; idx < W * H; idx += 256) {
            int yi = ylo + idx / W, xi = xlo + idx % W;
            int a = Loff[l] + yi * n + xi;
            if (!g_fg[a]) continue;
            float4 p = pb[a];
            float iou = masked_iou(B, p, true);
            if (iou > lvv[9]) {
                float v = iou;
#pragma unroll
                for (int k = 0; k < 10; k++)
                    if (v > lvv[k]) { float t2 = lvv[k]; lvv[k] = v; v = t2; }
            }
            float cx = f_mul(f_add((float)xi, 0.5f), s);
            float cy = f_mul(f_add((float)yi, 0.5f), s);
            if (is_cand(B, cx, cy, r)) {
                float lg = logf(f_add(iou, 1e-8f));
                float tv = t_exact(cls[((long long)b * A_N + a) * C_N + scls],
                                   obj[b * A_N + a]);
                float cl = -f_add(tv, g_sall[a]);
                float c = f_sub(cl, f_mul(3.0f, lg));
                int slot = atomicAdd(&sCnt, 1);
                if (slot < 96) { sKey[slot] = cost_key(c, a); sCiou[slot] = iou; }
            }
        }
    }
    int t = threadIdx.x;
#pragma unroll
    for (int k = 0; k < 10; k++) sV[t * 10 + k] = lvv[k];
    for (int st = 128; st > 0; st >>= 1) {
        __syncthreads();
        if (t < st) {
            int b1 = t * 10, b2 = (t + st) * 10;
            float mv[10]; int ii = 0, jj = 0;
#pragma unroll
            for (int k = 0; k < 10; k++) {
                float v1 = sV[b1 + min(ii, 9)], v2 = sV[b2 + min(jj, 9)];
                bool t1 = (jj >= 10) || ((ii < 10) && (v1 >= v2));
                mv[k] = t1 ? v1 : v2;
                if (t1) ii++; else jj++;
            }
#pragma unroll
            for (int k = 0; k < 10; k++) sV[b1 + k] = mv[k];
        }
    }
    __syncthreads();
    if (t == 0) {
        float sum = 0.f;
        for (int k = 0; k < 10; k++) sum = f_add(sum, sV[k]);
        int dk = (int)sum;
        dk = max(1, min(10, dk));
        sDk = dk; g_dk[g] = dk;
    }
    __syncthreads();
    int cnt = min(sCnt, 96);
    if (cnt >= 10) {
        if (t < cnt) {
            unsigned long long k0 = sKey[t];
            int rank = 0;
            for (int j = 0; j < cnt; j++) rank += (sKey[j] < k0);
            if (rank < sDk) {
                int a = (int)(k0 & 0xffffffffULL);
                atomicAdd(&g_cnt[a], 1);
                g_mgt[a] = g;
                g_miou[a] = sCiou[t];
            }
        }
    } else if (t == 0) {
        g_fb[g] = 1;
    }
}

// ---------------- K5: fallback scan (8-way split, rare) ----------------
__global__ __launch_bounds__(128) void k_fallback(
    const float* __restrict__ gt, const int* __restrict__ gtc,
    const float4* __restrict__ pb,
    const float* __restrict__ cls, const float* __restrict__ obj,
    const int* __restrict__ pbatch)
{
    int g = blockIdx.x >> 3, s = blockIdx.x & 7;
    if (!g_fb[g]) return;
    __shared__ GTBox sgt; __shared__ int scls;
    __shared__ unsigned long long sK[1280];
    if (threadIdx.x == 0) { sgt = make_gt(gt, g); scls = gtc[g]; }
    __syncthreads();
    GTBox B = sgt;
    long long b = (long long)(*pbatch);
    unsigned long long lk[10];
#pragma unroll
    for (int k = 0; k < 10; k++) lk[k] = 0xFFFFFFFFFFFFFFFFULL;
    int a0 = s * (A_N / 8);
    for (int a = a0 + threadIdx.x; a < a0 + A_N / 8; a += 128) {
        float4 p = pb[a];
        bool fg = g_fg[a] != 0;
        float iou = masked_iou(B, p, fg);
        float cx, cy, r;
        anchor_geom(a, cx, cy, r);
        bool cand = is_cand(B, cx, cy, r);
        float lg = logf(f_add(iou, 1e-8f));
        float tv = t_exact(cls[((long long)b * A_N + a) * C_N + scls], obj[b * A_N + a]);
        float cl = -f_add(tv, g_sall[a]);
        float c = f_sub(cl, f_mul(3.0f, lg));
        if (!cand) c = f_add(c, 100000.0f);
        if (!fg)   c = f_add(c, 1000000.0f);
        unsigned long long key = cost_key(c, a);
        if (key < lk[9]) {
#pragma unroll
            for (int k = 0; k < 10; k++)
                if (key < lk[k]) { unsigned long long t2 = lk[k]; lk[k] = key; key = t2; }
        }
    }
    int t = threadIdx.x;
#pragma unroll
    for (int k = 0; k < 10; k++) sK[t * 10 + k] = lk[k];
    for (int st = 64; st > 0; st >>= 1) {
        __syncthreads();
        if (t < st) {
            int b1 = t * 10, b2 = (t + st) * 10;
            unsigned long long mk[10]; int ii = 0, jj = 0;
#pragma unroll
            for (int k = 0; k < 10; k++) {
                unsigned long long v1 = sK[b1 + min(ii, 9)], v2 = sK[b2 + min(jj, 9)];
                bool t1 = (jj >= 10) || ((ii < 10) && (v1 <= v2));
                mk[k] = t1 ? v1 : v2;
                if (t1) ii++; else jj++;
            }
#pragma unroll
            for (int k = 0; k < 10; k++) sK[b1 + k] = mk[k];
        }
    }
    __syncthreads();
    if (t < 10) g_fkey[(g * 8 + s) * 10 + t] = sK[t];
}

// ---------------- K6: fallback merge + scatter ----------------
__global__ __launch_bounds__(128) void k_fbmerge(const float* __restrict__ gt,
                                                 const float4* __restrict__ pb)
{
    int g = blockIdx.x;
    if (!g_fb[g]) return;
    __shared__ unsigned long long sK[80];
    int t = threadIdx.x;
    if (t < 80) sK[t] = g_fkey[g * 80 + t];
    __syncthreads();
    if (t == 0) {
        GTBox B = make_gt(gt, g);
        int dk = g_dk[g];
        for (int k = 0; k < dk; k++) {
            int bi = 0; unsigned long long bv = 0xFFFFFFFFFFFFFFFFULL;
            for (int j = 0; j < 80; j++)
                if (sK[j] < bv) { bv = sK[j]; bi = j; }
            sK[bi] = 0xFFFFFFFFFFFFFFFFULL;
            int a = (int)(bv & 0xffffffffULL);
            atomicAdd(&g_cnt[a], 1);
            g_mgt[a] = g;
            g_miou[a] = masked_iou(B, pb[a], g_fg[a] != 0);
        }
    }
}

// ---------------- K7: finalize singles, collect multi ----------------
__global__ __launch_bounds__(256) void k_final(const int* __restrict__ gtc, float* __restrict__ out) {
    int a = blockIdx.x * blockDim.x + threadIdx.x;
    if (a >= A_N) return;
    int cnt = g_cnt[a];
    float cls = -1.f, fg = 0.f, iou = 0.f, ind = -1.f;
    if (cnt == 1) {
        int g = g_mgt[a];
        cls = (float)gtc[g]; fg = 1.f; iou = g_miou[a]; ind = (float)g;
        atomicAdd(&g_numfg, 1);
    } else if (cnt > 1) {
        fg = 1.f;
        atomicAdd(&g_numfg, 1);
        int m = atomicAdd(&g_mcnt, 1);
        g_multi[m] = a;
    }
    out[a] = cls;
    out[A_N + a] = fg;
    out[2 * A_N + a] = iou;
    out[3 * A_N + a] = ind;
}

// ---------------- K8: resolve multi-matched (warp per anchor) ----------------
__global__ __launch_bounds__(256) void k_multi(
    const float* __restrict__ gt, const int* __restrict__ gtc,
    const float4* __restrict__ pb, float* __restrict__ out,
    const float* __restrict__ cls, const float* __restrict__ obj,
    const int* __restrict__ pbatch)
{
    int w = (blockIdx.x * blockDim.x + threadIdx.x) >> 5;
    int lane = threadIdx.x & 31;
    int nw = (gridDim.x * blockDim.x) >> 5;
    if (w == 0 && lane == 0) out[4 * A_N] = (float)g_numfg;
    int M = g_mcnt;
    long long b = (long long)(*pbatch);
    for (int e = w; e < M; e += nw) {
        int a = g_multi[e];
        float4 p = pb[a];
        bool fg = g_fg[a] != 0;
        float cx, cy, r;
        anchor_geom(a, cx, cy, r);
        float sall = g_sall[a];
        float o = obj[b * A_N + a];
        float best = -FINF; int bg = 0x7fffffff;
        for (int g = lane; g < G_N; g += 32) {
            GTBox B = make_gt(gt, g);
            float iou = masked_iou(B, p, fg);
            bool cand = is_cand(B, cx, cy, r);
            float lg = logf(f_add(iou, 1e-8f));
            float tv = t_exact(cls[((long long)b * A_N + a) * C_N + gtc[g]], o);
            float cl = -f_add(tv, sall);
            float c = f_sub(cl, f_mul(3.0f, lg));
            if (!cand) c = f_add(c, 100000.0f);
            if (!fg)   c = f_add(c, 1000000.0f);
            if (c > best || (c == best && g < bg)) { best = c; bg = g; }
        }
#pragma unroll
        for (int o2 = 16; o2; o2 >>= 1) {
            float oc = __shfl_down_sync(0xffffffffu, best, o2);
            int og = __shfl_down_sync(0xffffffffu, bg, o2);
            if (oc > best || (oc == best && og < bg)) { best = oc; bg = og; }
        }
        bg = __shfl_sync(0xffffffffu, bg, 0);
        if (lane == 0) {
            GTBox B = make_gt(gt, bg);
            float iou = masked_iou(B, p, fg);
            out[a] = (float)gtc[bg];
            out[2 * A_N + a] = iou;
            out[3 * A_N + a] = (float)bg;
        }
    }
}

// ---------------- launch ----------------
extern "C" void kernel_launch(void* const* d_in, const int* in_sizes, int n_in,
                              void* d_out, int out_size) {
    const int*   batch = (const int*)d_in[0];
    const float* gt    = (const float*)d_in[3];
    const int*   gtc   = (const int*)d_in[4];
    const float* pb    = (const float*)d_in[5];
    const float* cp    = (const float*)d_in[9];
    const float* op    = (const float*)d_in[10];
    float* out = (float*)d_out;

    k_zero<<<(A_N + 255) / 256, 256>>>();
    k_sall_part<<<(A_N * 4 + 255) / 256, 256>>>(cp, op, batch);
    k_bounds<<<(A_N + 255) / 256, 256>>>((const float4*)pb);
    k_fgmark<<<G_N, 128>>>(gt);
    k_assign<<<G_N, 256>>>(gt, gtc, (const float4*)pb, cp, op, batch);
    k_fallback<<<G_N * 8, 128>>>(gt, gtc, (const float4*)pb, cp, op, batch);
    k_fbmerge<<<G_N, 128>>>(gt, (const float4*)pb);
    k_final<<<(A_N + 255) / 256, 256>>>(gtc, out);
    k_multi<<<64, 256>>>(gt, gtc, (const float4*)pb, out, cp, op, batch);
}

// round 6
// speedup vs baseline: 1.8172x; 1.8172x over previous
#include <cuda_runtime.h>
#include <math.h>

#define A_N 33600
#define G_N 300
#define C_N 80
#define FINF __int_as_float(0x7f800000)

// ---------------- scratch ----------------
__device__ float g_spart[A_N * 4];
__device__ float g_sall[A_N];
__device__ unsigned char g_fg[A_N];
__device__ int   g_cnt[A_N];
__device__ int   g_mgt[A_N];
__device__ float g_miou[A_N];
__device__ int   g_multi[A_N];
__device__ int   g_mcnt;
__device__ int   g_numfg;
__device__ int   g_Di[12];                     // per-level {exp,exn,eyp,eyn} float-as-int (>=0)
__device__ int   g_fb[G_N];
__device__ int   g_dk[G_N];
__device__ unsigned long long g_fkey[G_N * 8 * 10];

__device__ __forceinline__ float f_mul(float a, float b) { return __fmul_rn(a, b); }
__device__ __forceinline__ float f_add(float a, float b) { return __fadd_rn(a, b); }
__device__ __forceinline__ float f_sub(float a, float b) { return __fadd_rn(a, -b); }

struct GTBox { float x, y, tlx, tly, brx, bry, area; };

__device__ __forceinline__ GTBox make_gt(const float* __restrict__ gt, int g) {
    GTBox B;
    float gx = gt[g * 4 + 0], gy = gt[g * 4 + 1], gw = gt[g * 4 + 2], gh = gt[g * 4 + 3];
    B.x = gx; B.y = gy;
    B.tlx = f_sub(gx, f_mul(0.5f, gw));
    B.tly = f_sub(gy, f_mul(0.5f, gh));
    B.brx = f_add(gx, f_mul(0.5f, gw));
    B.bry = f_add(gy, f_mul(0.5f, gh));
    B.area = f_mul(gw, gh);
    return B;
}

__device__ __forceinline__ float masked_iou(const GTBox& B, float4 p, bool fg) {
    float hw = f_mul(0.5f, p.z), hh = f_mul(0.5f, p.w);
    float tlx = fmaxf(B.tlx, f_sub(p.x, hw));
    float tly = fmaxf(B.tly, f_sub(p.y, hh));
    float brx = fminf(B.brx, f_add(p.x, hw));
    float bry = fminf(B.bry, f_add(p.y, hh));
    float w = fmaxf(f_sub(brx, tlx), 0.f);
    float h = fmaxf(f_sub(bry, tly), 0.f);
    float inter = f_mul(w, h);
    float uni = f_sub(f_add(B.area, f_mul(p.z, p.w)), inter);
    float iou = inter / uni;
    return fg ? iou : 0.f;
}

__device__ __forceinline__ void anchor_geom(int a, float& cx, float& cy, float& r) {
    int xi, yi; float s;
    if (a < 25600)      { yi = a / 160;          xi = a - yi * 160;          s = 8.f;  r = 20.f; }
    else if (a < 32000) { int b = a - 25600; yi = b / 80;  xi = b - yi * 80;  s = 16.f; r = 40.f; }
    else                { int b = a - 32000; yi = b / 40;  xi = b - yi * 40;  s = 32.f; r = 80.f; }
    cx = f_mul(f_add((float)xi, 0.5f), s);
    cy = f_mul(f_add((float)yi, 0.5f), s);
}

__device__ __forceinline__ bool is_cand(const GTBox& B, float cx, float cy, float r) {
    bool inb = (cx > B.tlx) && (B.brx > cx) && (cy > B.tly) && (B.bry > cy);
    bool inc = (cx > f_sub(B.x, r)) && (f_add(B.x, r) > cx) &&
               (cy > f_sub(B.y, r)) && (f_add(B.y, r) > cy);
    return inb && inc;
}

__device__ __forceinline__ unsigned long long cost_key(float c, int a) {
    unsigned u = __float_as_uint(c);
    u ^= (((int)u >> 31) | 0x80000000u);
    return ((unsigned long long)u << 32) | (unsigned)a;
}

// exact t = log(p) - log1p(-p) (candidates / rare paths only)
__device__ __forceinline__ float t_exact(float z, float o) {
    float sz = 1.f / (1.f + expf(-z));
    float so = 1.f / (1.f + expf(-o));
    float p = sqrtf(f_mul(sz, so));
    p = fminf(fmaxf(p, 1e-7f), 1.0f - 1e-7f);
    return f_sub(logf(p), log1pf(-p));
}

// fast s_all term: w = clamp(1 - rsqrt((1+e^-z)(1+e^-o)), 1e-7, 1-1e-7)
__device__ __forceinline__ float wterm(float z, float Bo) {
    float v = __fmaf_rn(__expf(-z), Bo, Bo);    // (1+e^-z) * Bo
    float w = 1.f - rsqrtf(v);
    return fminf(fmaxf(w, 1e-7f), 1.f - 1e-7f);
}

// ---------------- K0: zero ----------------
__global__ void k_zero() {
    int i = blockIdx.x * blockDim.x + threadIdx.x;
    if (i < A_N) { g_cnt[i] = 0; g_fg[i] = 0; }
    if (i < G_N) g_fb[i] = 0;
    if (i < 12)  g_Di[i] = 0;
    if (i == 0) { g_mcnt = 0; g_numfg = 0; }
}

// ---------------- K1: s_all partials — thread per (anchor, class-quarter) ----------------
__global__ __launch_bounds__(256) void k_sall_part(
    const float* __restrict__ cls, const float* __restrict__ obj,
    const int* __restrict__ pbatch)
{
    int idx = blockIdx.x * blockDim.x + threadIdx.x;
    if (idx >= A_N * 4) return;
    int a = idx >> 2, q = idx & 3;
    long long b = (long long)(*pbatch);
    float Bo = 1.f + __expf(-obj[b * A_N + a]);
    const float4* __restrict__ row =
        (const float4*)(cls + ((long long)b * A_N + a) * C_N + q * 20);
    float prod = 1.f;
    int ecnt = 0;
#pragma unroll
    for (int k = 0; k < 5; k++) {
        float4 zv = row[k];
        prod = prod * wterm(zv.x, Bo);
        prod = prod * wterm(zv.y, Bo);
        prod = prod * wterm(zv.z, Bo);
        prod = prod * wterm(zv.w, Bo);
        unsigned bb = __float_as_uint(prod);     // prod > 0 always
        ecnt += (int)(bb >> 23) - 127;
        prod = __uint_as_float((bb & 0x007FFFFFu) | 0x3F800000u);
    }
    g_spart[idx] = __fmaf_rn((float)ecnt, 0.6931471805599453f, __logf(prod));
}

// ---------------- K2: per-level pred-box extent bounds + s_all combine ----------------
__global__ __launch_bounds__(256) void k_bounds(const float4* __restrict__ pb) {
    int a = blockIdx.x * blockDim.x + threadIdx.x;
    if (a >= A_N) return;
    g_sall[a] = f_add(f_add(f_add(g_spart[a * 4], g_spart[a * 4 + 1]),
                            g_spart[a * 4 + 2]), g_spart[a * 4 + 3]);
    float cx, cy, r;
    anchor_geom(a, cx, cy, r);
    int lvl = (a < 25600) ? 0 : (a < 32000 ? 1 : 2);
    float4 p = pb[a];
    float hw = f_mul(0.5f, p.z), hh = f_mul(0.5f, p.w);
    float exp_ = fmaxf(f_sub(f_add(p.x, hw), cx), 0.f);
    float exn  = fmaxf(f_sub(cx, f_sub(p.x, hw)), 0.f);
    float eyp  = fmaxf(f_sub(f_add(p.y, hh), cy), 0.f);
    float eyn  = fmaxf(f_sub(cy, f_sub(p.y, hh)), 0.f);
#pragma unroll
    for (int o = 16; o; o >>= 1) {
        exp_ = fmaxf(exp_, __shfl_down_sync(0xffffffffu, exp_, o));
        exn  = fmaxf(exn,  __shfl_down_sync(0xffffffffu, exn,  o));
        eyp  = fmaxf(eyp,  __shfl_down_sync(0xffffffffu, eyp,  o));
        eyn  = fmaxf(eyn,  __shfl_down_sync(0xffffffffu, eyn,  o));
    }
    if ((threadIdx.x & 31) == 0) {   // warps are level-homogeneous (boundaries %32==0)
        atomicMax(&g_Di[lvl * 4 + 0], __float_as_int(exp_));
        atomicMax(&g_Di[lvl * 4 + 1], __float_as_int(exn));
        atomicMax(&g_Di[lvl * 4 + 2], __float_as_int(eyp));
        atomicMax(&g_Di[lvl * 4 + 3], __float_as_int(eyn));
    }
}

// ---------------- K3: fg marking per gt window ----------------
__global__ __launch_bounds__(128) void k_fgmark(const float* __restrict__ gt) {
    int g = blockIdx.x;
    __shared__ GTBox sgt;
    if (threadIdx.x == 0) sgt = make_gt(gt, g);
    __syncthreads();
    GTBox B = sgt;
    const int Loff[3] = {0, 25600, 32000}, Ln[3] = {160, 80, 40};
    const float Ls[3] = {8.f, 16.f, 32.f}, Lr[3] = {20.f, 40.f, 80.f};
    for (int l = 0; l < 3; l++) {
        float s = Ls[l], r = Lr[l];
        int n = Ln[l];
        float xlo_f = fminf(B.tlx, f_sub(B.x, r)), xhi_f = fmaxf(B.brx, f_add(B.x, r));
        float ylo_f = fminf(B.tly, f_sub(B.y, r)), yhi_f = fmaxf(B.bry, f_add(B.y, r));
        int xlo = max(0, (int)floorf(xlo_f / s - 0.5f) - 1);
        int xhi = min(n - 1, (int)ceilf(xhi_f / s - 0.5f) + 1);
        int ylo = max(0, (int)floorf(ylo_f / s - 0.5f) - 1);
        int yhi = min(n - 1, (int)ceilf(yhi_f / s - 0.5f) + 1);
        if (xhi < xlo || yhi < ylo) continue;
        int W = xhi - xlo + 1, H = yhi - ylo + 1;
        for (int idx = threadIdx.x; idx < W * H; idx += 128) {
            int yi = ylo + idx / W, xi = xlo + idx % W;
            float cx = f_mul(f_add((float)xi, 0.5f), s);
            float cy = f_mul(f_add((float)yi, 0.5f), s);
            bool inb = (cx > B.tlx) && (B.brx > cx) && (cy > B.tly) && (B.bry > cy);
            bool inc = (cx > f_sub(B.x, r)) && (f_add(B.x, r) > cx) &&
                       (cy > f_sub(B.y, r)) && (f_add(B.y, r) > cy);
            if (inb || inc) g_fg[Loff[l] + yi * n + xi] = 1;
        }
    }
}

// ---------------- K4: fused windowed assignment per gt ----------------
__global__ __launch_bounds__(256) void k_assign(
    const float* __restrict__ gt, const int* __restrict__ gtc,
    const float4* __restrict__ pb,
    const float* __restrict__ cls, const float* __restrict__ obj,
    const int* __restrict__ pbatch)
{
    int g = blockIdx.x;
    __shared__ GTBox sgt; __shared__ int scls;
    __shared__ float sV[2560];
    __shared__ unsigned long long sKey[96];
    __shared__ float sCiou[96];
    __shared__ int sCnt, sDk;
    if (threadIdx.x == 0) { sgt = make_gt(gt, g); scls = gtc[g]; sCnt = 0; }
    __syncthreads();
    GTBox B = sgt;
    long long b = (long long)(*pbatch);
    const int Loff[3] = {0, 25600, 32000}, Ln[3] = {160, 80, 40};
    const float Ls[3] = {8.f, 16.f, 32.f}, Lr[3] = {20.f, 40.f, 80.f};
    float lvv[10];
#pragma unroll
    for (int k = 0; k < 10; k++) lvv[k] = 0.f;

    for (int l = 0; l < 3; l++) {
        float s = Ls[l], r = Lr[l];
        int n = Ln[l];
        float Dxp = f_add(__int_as_float(g_Di[l * 4 + 0]), 1.0f);
        float Dxn = f_add(__int_as_float(g_Di[l * 4 + 1]), 1.0f);
        float Dyp = f_add(__int_as_float(g_Di[l * 4 + 2]), 1.0f);
        float Dyn = f_add(__int_as_float(g_Di[l * 4 + 3]), 1.0f);
        int xlo = max(0, (int)floorf((B.tlx - Dxp) / s - 0.5f) - 1);
        int xhi = min(n - 1, (int)ceilf((B.brx + Dxn) / s - 0.5f) + 1);
        int ylo = max(0, (int)floorf((B.tly - Dyp) / s - 0.5f) - 1);
        int yhi = min(n - 1, (int)ceilf((B.bry + Dyn) / s - 0.5f) + 1);
        if (xhi < xlo || yhi < ylo) continue;
        int W = xhi - xlo + 1, H = yhi - ylo + 1;
        for (int idx = threadIdx.x; idx < W * H; idx += 256) {
            int yi = ylo + idx / W, xi = xlo + idx % W;
            int a = Loff[l] + yi * n + xi;
            if (!g_fg[a]) continue;
            float4 p = pb[a];
            float iou = masked_iou(B, p, true);
            if (iou > lvv[9]) {
                float v = iou;
#pragma unroll
                for (int k = 0; k < 10; k++)
                    if (v > lvv[k]) { float t2 = lvv[k]; lvv[k] = v; v = t2; }
            }
            float cx = f_mul(f_add((float)xi, 0.5f), s);
            float cy = f_mul(f_add((float)yi, 0.5f), s);
            if (is_cand(B, cx, cy, r)) {
                float lg = logf(f_add(iou, 1e-8f));
                float tv = t_exact(cls[((long long)b * A_N + a) * C_N + scls],
                                   obj[b * A_N + a]);
                float cl = -f_add(tv, g_sall[a]);
                float c = f_sub(cl, f_mul(3.0f, lg));
                int slot = atomicAdd(&sCnt, 1);
                if (slot < 96) { sKey[slot] = cost_key(c, a); sCiou[slot] = iou; }
            }
        }
    }
    int t = threadIdx.x;
#pragma unroll
    for (int k = 0; k < 10; k++) sV[t * 10 + k] = lvv[k];
    for (int st = 128; st > 0; st >>= 1) {
        __syncthreads();
        if (t < st) {
            int b1 = t * 10, b2 = (t + st) * 10;
            float mv[10]; int ii = 0, jj = 0;
#pragma unroll
            for (int k = 0; k < 10; k++) {
                float v1 = sV[b1 + min(ii, 9)], v2 = sV[b2 + min(jj, 9)];
                bool t1 = (jj >= 10) || ((ii < 10) && (v1 >= v2));
                mv[k] = t1 ? v1 : v2;
                if (t1) ii++; else jj++;
            }
#pragma unroll
            for (int k = 0; k < 10; k++) sV[b1 + k] = mv[k];
        }
    }
    __syncthreads();
    if (t == 0) {
        float sum = 0.f;
        for (int k = 0; k < 10; k++) sum = f_add(sum, sV[k]);
        int dk = (int)sum;
        dk = max(1, min(10, dk));
        sDk = dk; g_dk[g] = dk;
    }
    __syncthreads();
    int cnt = min(sCnt, 96);
    // candidates always rank strictly above non-candidates (cost gap ~1e5),
    // so candidate-only selection is exact whenever cnt >= dk.
    if (cnt >= sDk) {
        if (t < cnt) {
            unsigned long long k0 = sKey[t];
            int rank = 0;
            for (int j = 0; j < cnt; j++) rank += (sKey[j] < k0);
            if (rank < sDk) {
                int a = (int)(k0 & 0xffffffffULL);
                atomicAdd(&g_cnt[a], 1);
                g_mgt[a] = g;
                g_miou[a] = sCiou[t];
            }
        }
    } else if (t == 0) {
        g_fb[g] = 1;
    }
}

// ---------------- K5: fallback scan (8-way split, now extremely rare) ----------------
__global__ __launch_bounds__(128) void k_fallback(
    const float* __restrict__ gt, const int* __restrict__ gtc,
    const float4* __restrict__ pb,
    const float* __restrict__ cls, const float* __restrict__ obj,
    const int* __restrict__ pbatch)
{
    int g = blockIdx.x >> 3, s = blockIdx.x & 7;
    if (!g_fb[g]) return;
    __shared__ GTBox sgt; __shared__ int scls;
    __shared__ unsigned long long sK[1280];
    if (threadIdx.x == 0) { sgt = make_gt(gt, g); scls = gtc[g]; }
    __syncthreads();
    GTBox B = sgt;
    long long b = (long long)(*pbatch);
    unsigned long long lk[10];
#pragma unroll
    for (int k = 0; k < 10; k++) lk[k] = 0xFFFFFFFFFFFFFFFFULL;
    int a0 = s * (A_N / 8);
    for (int a = a0 + threadIdx.x; a < a0 + A_N / 8; a += 128) {
        float4 p = pb[a];
        bool fg = g_fg[a] != 0;
        float iou = masked_iou(B, p, fg);
        float cx, cy, r;
        anchor_geom(a, cx, cy, r);
        bool cand = is_cand(B, cx, cy, r);
        float lg = logf(f_add(iou, 1e-8f));
        float tv = t_exact(cls[((long long)b * A_N + a) * C_N + scls], obj[b * A_N + a]);
        float cl = -f_add(tv, g_sall[a]);
        float c = f_sub(cl, f_mul(3.0f, lg));
        if (!cand) c = f_add(c, 100000.0f);
        if (!fg)   c = f_add(c, 1000000.0f);
        unsigned long long key = cost_key(c, a);
        if (key < lk[9]) {
#pragma unroll
            for (int k = 0; k < 10; k++)
                if (key < lk[k]) { unsigned long long t2 = lk[k]; lk[k] = key; key = t2; }
        }
    }
    int t = threadIdx.x;
#pragma unroll
    for (int k = 0; k < 10; k++) sK[t * 10 + k] = lk[k];
    for (int st = 64; st > 0; st >>= 1) {
        __syncthreads();
        if (t < st) {
            int b1 = t * 10, b2 = (t + st) * 10;
            unsigned long long mk[10]; int ii = 0, jj = 0;
#pragma unroll
            for (int k = 0; k < 10; k++) {
                unsigned long long v1 = sK[b1 + min(ii, 9)], v2 = sK[b2 + min(jj, 9)];
                bool t1 = (jj >= 10) || ((ii < 10) && (v1 <= v2));
                mk[k] = t1 ? v1 : v2;
                if (t1) ii++; else jj++;
            }
#pragma unroll
            for (int k = 0; k < 10; k++) sK[b1 + k] = mk[k];
        }
    }
    __syncthreads();
    if (t < 10) g_fkey[(g * 8 + s) * 10 + t] = sK[t];
}

// ---------------- K6: fallback merge + scatter ----------------
__global__ __launch_bounds__(128) void k_fbmerge(const float* __restrict__ gt,
                                                 const float4* __restrict__ pb)
{
    int g = blockIdx.x;
    if (!g_fb[g]) return;
    __shared__ unsigned long long sK[80];
    int t = threadIdx.x;
    if (t < 80) sK[t] = g_fkey[g * 80 + t];
    __syncthreads();
    if (t == 0) {
        GTBox B = make_gt(gt, g);
        int dk = g_dk[g];
        for (int k = 0; k < dk; k++) {
            int bi = 0; unsigned long long bv = 0xFFFFFFFFFFFFFFFFULL;
            for (int j = 0; j < 80; j++)
                if (sK[j] < bv) { bv = sK[j]; bi = j; }
            sK[bi] = 0xFFFFFFFFFFFFFFFFULL;
            int a = (int)(bv & 0xffffffffULL);
            atomicAdd(&g_cnt[a], 1);
            g_mgt[a] = g;
            g_miou[a] = masked_iou(B, pb[a], g_fg[a] != 0);
        }
    }
}

// ---------------- K7: finalize singles, collect multi ----------------
__global__ __launch_bounds__(256) void k_final(const int* __restrict__ gtc, float* __restrict__ out) {
    int a = blockIdx.x * blockDim.x + threadIdx.x;
    if (a >= A_N) return;
    int cnt = g_cnt[a];
    float cls = -1.f, fg = 0.f, iou = 0.f, ind = -1.f;
    if (cnt == 1) {
        int g = g_mgt[a];
        cls = (float)gtc[g]; fg = 1.f; iou = g_miou[a]; ind = (float)g;
        atomicAdd(&g_numfg, 1);
    } else if (cnt > 1) {
        fg = 1.f;
        atomicAdd(&g_numfg, 1);
        int m = atomicAdd(&g_mcnt, 1);
        g_multi[m] = a;
    }
    out[a] = cls;
    out[A_N + a] = fg;
    out[2 * A_N + a] = iou;
    out[3 * A_N + a] = ind;
}

// ---------------- K8: resolve multi-matched (warp per anchor) ----------------
__global__ __launch_bounds__(256) void k_multi(
    const float* __restrict__ gt, const int* __restrict__ gtc,
    const float4* __restrict__ pb, float* __restrict__ out,
    const float* __restrict__ cls, const float* __restrict__ obj,
    const int* __restrict__ pbatch)
{
    int w = (blockIdx.x * blockDim.x + threadIdx.x) >> 5;
    int lane = threadIdx.x & 31;
    int nw = (gridDim.x * blockDim.x) >> 5;
    if (w == 0 && lane == 0) out[4 * A_N] = (float)g_numfg;
    int M = g_mcnt;
    long long b = (long long)(*pbatch);
    for (int e = w; e < M; e += nw) {
        int a = g_multi[e];
        float4 p = pb[a];
        bool fg = g_fg[a] != 0;
        float cx, cy, r;
        anchor_geom(a, cx, cy, r);
        float sall = g_sall[a];
        float o = obj[b * A_N + a];
        float best = -FINF; int bg = 0x7fffffff;
        for (int g = lane; g < G_N; g += 32) {
            GTBox B = make_gt(gt, g);
            float iou = masked_iou(B, p, fg);
            bool cand = is_cand(B, cx, cy, r);
            float lg = logf(f_add(iou, 1e-8f));
            float tv = t_exact(cls[((long long)b * A_N + a) * C_N + gtc[g]], o);
            float cl = -f_add(tv, sall);
            float c = f_sub(cl, f_mul(3.0f, lg));
            if (!cand) c = f_add(c, 100000.0f);
            if (!fg)   c = f_add(c, 1000000.0f);
            if (c > best || (c == best && g < bg)) { best = c; bg = g; }
        }
#pragma unroll
        for (int o2 = 16; o2; o2 >>= 1) {
            float oc = __shfl_down_sync(0xffffffffu, best, o2);
            int og = __shfl_down_sync(0xffffffffu, bg, o2);
            if (oc > best || (oc == best && og < bg)) { best = oc; bg = og; }
        }
        bg = __shfl_sync(0xffffffffu, bg, 0);
        if (lane == 0) {
            GTBox B = make_gt(gt, bg);
            float iou = masked_iou(B, p, fg);
            out[a] = (float)gtc[bg];
            out[2 * A_N + a] = iou;
            out[3 * A_N + a] = (float)bg;
        }
    }
}

// ---------------- launch ----------------
extern "C" void kernel_launch(void* const* d_in, const int* in_sizes, int n_in,
                              void* d_out, int out_size) {
    const int*   batch = (const int*)d_in[0];
    const float* gt    = (const float*)d_in[3];
    const int*   gtc   = (const int*)d_in[4];
    const float* pb    = (const float*)d_in[5];
    const float* cp    = (const float*)d_in[9];
    const float* op    = (const float*)d_in[10];
    float* out = (float*)d_out;

    k_zero<<<(A_N + 255) / 256, 256>>>();
    k_sall_part<<<(A_N * 4 + 255) / 256, 256>>>(cp, op, batch);
    k_bounds<<<(A_N + 255) / 256, 256>>>((const float4*)pb);
    k_fgmark<<<G_N, 128>>>(gt);
    k_assign<<<G_N, 256>>>(gt, gtc, (const float4*)pb, cp, op, batch);
    k_fallback<<<G_N * 8, 128>>>(gt, gtc, (const float4*)pb, cp, op, batch);
    k_fbmerge<<<G_N, 128>>>(gt, (const float4*)pb);
    k_final<<<(A_N + 255) / 256, 256>>>(gtc, out);
    k_multi<<<64, 256>>>(gt, gtc, (const float4*)pb, out, cp, op, batch);
}

// round 7
// speedup vs baseline: 1.8489x; 1.0175x over previous
#include <cuda_runtime.h>
#include <math.h>

#define A_N 33600
#define G_N 300
#define C_N 80
#define FINF __int_as_float(0x7f800000)

// ---------------- scratch ----------------
__device__ float g_spart[A_N * 4];
__device__ float g_sall[A_N];
__device__ unsigned char g_fg[A_N];
__device__ unsigned char g_isc[A_N];           // candidate-of-some-gt mask
__device__ int   g_cnt[A_N];
__device__ int   g_mgt[A_N];
__device__ float g_miou[A_N];
__device__ int   g_multi[A_N];
__device__ int   g_mcnt;
__device__ int   g_numfg;
__device__ int   g_anyfb;
__device__ int   g_Di[12];                     // per-level {exp,exn,eyp,eyn} float-as-int (>=0)
__device__ int   g_fb[G_N];
__device__ int   g_dk[G_N];
__device__ unsigned long long g_fkey[G_N * 8 * 10];

__device__ __forceinline__ float f_mul(float a, float b) { return __fmul_rn(a, b); }
__device__ __forceinline__ float f_add(float a, float b) { return __fadd_rn(a, b); }
__device__ __forceinline__ float f_sub(float a, float b) { return __fadd_rn(a, -b); }

struct GTBox { float x, y, tlx, tly, brx, bry, area; };

__device__ __forceinline__ GTBox make_gt(const float* __restrict__ gt, int g) {
    GTBox B;
    float gx = gt[g * 4 + 0], gy = gt[g * 4 + 1], gw = gt[g * 4 + 2], gh = gt[g * 4 + 3];
    B.x = gx; B.y = gy;
    B.tlx = f_sub(gx, f_mul(0.5f, gw));
    B.tly = f_sub(gy, f_mul(0.5f, gh));
    B.brx = f_add(gx, f_mul(0.5f, gw));
    B.bry = f_add(gy, f_mul(0.5f, gh));
    B.area = f_mul(gw, gh);
    return B;
}

__device__ __forceinline__ float masked_iou(const GTBox& B, float4 p, bool fg) {
    float hw = f_mul(0.5f, p.z), hh = f_mul(0.5f, p.w);
    float tlx = fmaxf(B.tlx, f_sub(p.x, hw));
    float tly = fmaxf(B.tly, f_sub(p.y, hh));
    float brx = fminf(B.brx, f_add(p.x, hw));
    float bry = fminf(B.bry, f_add(p.y, hh));
    float w = fmaxf(f_sub(brx, tlx), 0.f);
    float h = fmaxf(f_sub(bry, tly), 0.f);
    float inter = f_mul(w, h);
    float uni = f_sub(f_add(B.area, f_mul(p.z, p.w)), inter);
    float iou = inter / uni;
    return fg ? iou : 0.f;
}

__device__ __forceinline__ void anchor_geom(int a, float& cx, float& cy, float& r) {
    int xi, yi; float s;
    if (a < 25600)      { yi = a / 160;          xi = a - yi * 160;          s = 8.f;  r = 20.f; }
    else if (a < 32000) { int b = a - 25600; yi = b / 80;  xi = b - yi * 80;  s = 16.f; r = 40.f; }
    else                { int b = a - 32000; yi = b / 40;  xi = b - yi * 40;  s = 32.f; r = 80.f; }
    cx = f_mul(f_add((float)xi, 0.5f), s);
    cy = f_mul(f_add((float)yi, 0.5f), s);
}

__device__ __forceinline__ bool is_cand(const GTBox& B, float cx, float cy, float r) {
    bool inb = (cx > B.tlx) && (B.brx > cx) && (cy > B.tly) && (B.bry > cy);
    bool inc = (cx > f_sub(B.x, r)) && (f_add(B.x, r) > cx) &&
               (cy > f_sub(B.y, r)) && (f_add(B.y, r) > cy);
    return inb && inc;
}

__device__ __forceinline__ unsigned long long cost_key(float c, int a) {
    unsigned u = __float_as_uint(c);
    u ^= (((int)u >> 31) | 0x80000000u);
    return ((unsigned long long)u << 32) | (unsigned)a;
}

// exact t = log(p) - log1p(-p) (candidates / rare paths only)
__device__ __forceinline__ float t_exact(float z, float o) {
    float sz = 1.f / (1.f + expf(-z));
    float so = 1.f / (1.f + expf(-o));
    float p = sqrtf(f_mul(sz, so));
    p = fminf(fmaxf(p, 1e-7f), 1.0f - 1e-7f);
    return f_sub(logf(p), log1pf(-p));
}

// fast s_all term: w = clamp(1 - rsqrt((1+e^-z)(1+e^-o)), 1e-7, 1-1e-7)
__device__ __forceinline__ float wterm(float z, float Bo) {
    float v = __fmaf_rn(__expf(-z), Bo, Bo);    // (1+e^-z) * Bo
    float w = 1.f - rsqrtf(v);
    return fminf(fmaxf(w, 1e-7f), 1.f - 1e-7f);
}

// one class-quarter partial of s_all (product + exponent stripping)
__device__ __forceinline__ float sall_quarter(const float4* __restrict__ row, float Bo) {
    float prod = 1.f;
    int ecnt = 0;
#pragma unroll
    for (int k = 0; k < 5; k++) {
        float4 zv = row[k];
        prod = prod * wterm(zv.x, Bo);
        prod = prod * wterm(zv.y, Bo);
        prod = prod * wterm(zv.z, Bo);
        prod = prod * wterm(zv.w, Bo);
        unsigned bb = __float_as_uint(prod);     // prod > 0 always
        ecnt += (int)(bb >> 23) - 127;
        prod = __uint_as_float((bb & 0x007FFFFFu) | 0x3F800000u);
    }
    return __fmaf_rn((float)ecnt, 0.6931471805599453f, __logf(prod));
}

// ---------------- K0: zero ----------------
__global__ void k_zero() {
    int i = blockIdx.x * blockDim.x + threadIdx.x;
    if (i < A_N) { g_cnt[i] = 0; g_fg[i] = 0; g_isc[i] = 0; }
    if (i < G_N) g_fb[i] = 0;
    if (i < 12)  g_Di[i] = 0;
    if (i == 0) { g_mcnt = 0; g_numfg = 0; g_anyfb = 0; }
}

// ---------------- K1: fg + candidate marking per gt window ----------------
__global__ __launch_bounds__(128) void k_fgmark(const float* __restrict__ gt) {
    int g = blockIdx.x;
    __shared__ GTBox sgt;
    if (threadIdx.x == 0) sgt = make_gt(gt, g);
    __syncthreads();
    GTBox B = sgt;
    const int Loff[3] = {0, 25600, 32000}, Ln[3] = {160, 80, 40};
    const float Ls[3] = {8.f, 16.f, 32.f}, Lr[3] = {20.f, 40.f, 80.f};
    for (int l = 0; l < 3; l++) {
        float s = Ls[l], r = Lr[l];
        int n = Ln[l];
        float xlo_f = fminf(B.tlx, f_sub(B.x, r)), xhi_f = fmaxf(B.brx, f_add(B.x, r));
        float ylo_f = fminf(B.tly, f_sub(B.y, r)), yhi_f = fmaxf(B.bry, f_add(B.y, r));
        int xlo = max(0, (int)floorf(xlo_f / s - 0.5f) - 1);
        int xhi = min(n - 1, (int)ceilf(xhi_f / s - 0.5f) + 1);
        int ylo = max(0, (int)floorf(ylo_f / s - 0.5f) - 1);
        int yhi = min(n - 1, (int)ceilf(yhi_f / s - 0.5f) + 1);
        if (xhi < xlo || yhi < ylo) continue;
        int W = xhi - xlo + 1, H = yhi - ylo + 1;
        for (int idx = threadIdx.x; idx < W * H; idx += 128) {
            int yi = ylo + idx / W, xi = xlo + idx % W;
            float cx = f_mul(f_add((float)xi, 0.5f), s);
            float cy = f_mul(f_add((float)yi, 0.5f), s);
            bool inb = (cx > B.tlx) && (B.brx > cx) && (cy > B.tly) && (B.bry > cy);
            bool inc = (cx > f_sub(B.x, r)) && (f_add(B.x, r) > cx) &&
                       (cy > f_sub(B.y, r)) && (f_add(B.y, r) > cy);
            int a = Loff[l] + yi * n + xi;
            if (inb || inc) g_fg[a] = 1;
            if (inb && inc) g_isc[a] = 1;
        }
    }
}

// ---------------- K2: s_all partials — candidates only ----------------
__global__ __launch_bounds__(256) void k_sall_cand(
    const float* __restrict__ cls, const float* __restrict__ obj,
    const int* __restrict__ pbatch)
{
    int idx = blockIdx.x * blockDim.x + threadIdx.x;
    if (idx >= A_N * 4) return;
    int a = idx >> 2, q = idx & 3;
    if (!g_isc[a]) return;
    long long b = (long long)(*pbatch);
    float Bo = 1.f + __expf(-obj[b * A_N + a]);
    const float4* __restrict__ row =
        (const float4*)(cls + ((long long)b * A_N + a) * C_N + q * 20);
    g_spart[idx] = sall_quarter(row, Bo);
}

// ---------------- K3: per-level pred-box extent bounds + s_all combine ----------------
__global__ __launch_bounds__(256) void k_bounds(const float4* __restrict__ pb) {
    int a = blockIdx.x * blockDim.x + threadIdx.x;
    if (a >= A_N) return;
    if (g_isc[a])
        g_sall[a] = f_add(f_add(f_add(g_spart[a * 4], g_spart[a * 4 + 1]),
                                g_spart[a * 4 + 2]), g_spart[a * 4 + 3]);
    float cx, cy, r;
    anchor_geom(a, cx, cy, r);
    int lvl = (a < 25600) ? 0 : (a < 32000 ? 1 : 2);
    float4 p = pb[a];
    float hw = f_mul(0.5f, p.z), hh = f_mul(0.5f, p.w);
    float exp_ = fmaxf(f_sub(f_add(p.x, hw), cx), 0.f);
    float exn  = fmaxf(f_sub(cx, f_sub(p.x, hw)), 0.f);
    float eyp  = fmaxf(f_sub(f_add(p.y, hh), cy), 0.f);
    float eyn  = fmaxf(f_sub(cy, f_sub(p.y, hh)), 0.f);
#pragma unroll
    for (int o = 16; o; o >>= 1) {
        exp_ = fmaxf(exp_, __shfl_down_sync(0xffffffffu, exp_, o));
        exn  = fmaxf(exn,  __shfl_down_sync(0xffffffffu, exn,  o));
        eyp  = fmaxf(eyp,  __shfl_down_sync(0xffffffffu, eyp,  o));
        eyn  = fmaxf(eyn,  __shfl_down_sync(0xffffffffu, eyn,  o));
    }
    if ((threadIdx.x & 31) == 0) {   // warps are level-homogeneous (boundaries %32==0)
        atomicMax(&g_Di[lvl * 4 + 0], __float_as_int(exp_));
        atomicMax(&g_Di[lvl * 4 + 1], __float_as_int(exn));
        atomicMax(&g_Di[lvl * 4 + 2], __float_as_int(eyp));
        atomicMax(&g_Di[lvl * 4 + 3], __float_as_int(eyn));
    }
}

// ---------------- K4: fused windowed assignment per gt ----------------
__global__ __launch_bounds__(256) void k_assign(
    const float* __restrict__ gt, const int* __restrict__ gtc,
    const float4* __restrict__ pb,
    const float* __restrict__ cls, const float* __restrict__ obj,
    const int* __restrict__ pbatch)
{
    int g = blockIdx.x;
    __shared__ GTBox sgt; __shared__ int scls;
    __shared__ float sV[2560];
    __shared__ unsigned long long sKey[96];
    __shared__ float sCiou[96];
    __shared__ int sCnt, sDk;
    if (threadIdx.x == 0) { sgt = make_gt(gt, g); scls = gtc[g]; sCnt = 0; }
    __syncthreads();
    GTBox B = sgt;
    long long b = (long long)(*pbatch);
    const int Loff[3] = {0, 25600, 32000}, Ln[3] = {160, 80, 40};
    const float Ls[3] = {8.f, 16.f, 32.f}, Lr[3] = {20.f, 40.f, 80.f};
    float lvv[10];
#pragma unroll
    for (int k = 0; k < 10; k++) lvv[k] = 0.f;

    for (int l = 0; l < 3; l++) {
        float s = Ls[l], r = Lr[l];
        int n = Ln[l];
        float Dxp = f_add(__int_as_float(g_Di[l * 4 + 0]), 1.0f);
        float Dxn = f_add(__int_as_float(g_Di[l * 4 + 1]), 1.0f);
        float Dyp = f_add(__int_as_float(g_Di[l * 4 + 2]), 1.0f);
        float Dyn = f_add(__int_as_float(g_Di[l * 4 + 3]), 1.0f);
        int xlo = max(0, (int)floorf((B.tlx - Dxp) / s - 0.5f) - 1);
        int xhi = min(n - 1, (int)ceilf((B.brx + Dxn) / s - 0.5f) + 1);
        int ylo = max(0, (int)floorf((B.tly - Dyp) / s - 0.5f) - 1);
        int yhi = min(n - 1, (int)ceilf((B.bry + Dyn) / s - 0.5f) + 1);
        if (xhi < xlo || yhi < ylo) continue;
        int W = xhi - xlo + 1, H = yhi - ylo + 1;
        for (int idx = threadIdx.x; idx < W * H; idx += 256) {
            int yi = ylo + idx / W, xi = xlo + idx % W;
            int a = Loff[l] + yi * n + xi;
            if (!g_fg[a]) continue;
            float4 p = pb[a];
            float iou = masked_iou(B, p, true);
            if (iou > lvv[9]) {
                float v = iou;
#pragma unroll
                for (int k = 0; k < 10; k++)
                    if (v > lvv[k]) { float t2 = lvv[k]; lvv[k] = v; v = t2; }
            }
            float cx = f_mul(f_add((float)xi, 0.5f), s);
            float cy = f_mul(f_add((float)yi, 0.5f), s);
            if (is_cand(B, cx, cy, r)) {
                float lg = logf(f_add(iou, 1e-8f));
                float tv = t_exact(cls[((long long)b * A_N + a) * C_N + scls],
                                   obj[b * A_N + a]);
                float cl = -f_add(tv, g_sall[a]);
                float c = f_sub(cl, f_mul(3.0f, lg));
                int slot = atomicAdd(&sCnt, 1);
                if (slot < 96) { sKey[slot] = cost_key(c, a); sCiou[slot] = iou; }
            }
        }
    }
    int t = threadIdx.x;
#pragma unroll
    for (int k = 0; k < 10; k++) sV[t * 10 + k] = lvv[k];
    for (int st = 128; st > 0; st >>= 1) {
        __syncthreads();
        if (t < st) {
            int b1 = t * 10, b2 = (t + st) * 10;
            float mv[10]; int ii = 0, jj = 0;
#pragma unroll
            for (int k = 0; k < 10; k++) {
                float v1 = sV[b1 + min(ii, 9)], v2 = sV[b2 + min(jj, 9)];
                bool t1 = (jj >= 10) || ((ii < 10) && (v1 >= v2));
                mv[k] = t1 ? v1 : v2;
                if (t1) ii++; else jj++;
            }
#pragma unroll
            for (int k = 0; k < 10; k++) sV[b1 + k] = mv[k];
        }
    }
    __syncthreads();
    if (t == 0) {
        float sum = 0.f;
        for (int k = 0; k < 10; k++) sum = f_add(sum, sV[k]);
        int dk = (int)sum;
        dk = max(1, min(10, dk));
        sDk = dk; g_dk[g] = dk;
    }
    __syncthreads();
    int cnt = min(sCnt, 96);
    // candidates always rank strictly above non-candidates (cost gap ~1e5),
    // so candidate-only selection is exact whenever cnt >= dk.
    if (cnt >= sDk) {
        if (t < cnt) {
            unsigned long long k0 = sKey[t];
            int rank = 0;
            for (int j = 0; j < cnt; j++) rank += (sKey[j] < k0);
            if (rank < sDk) {
                int a = (int)(k0 & 0xffffffffULL);
                atomicAdd(&g_cnt[a], 1);
                g_mgt[a] = g;
                g_miou[a] = sCiou[t];
            }
        }
    } else if (t == 0) {
        g_fb[g] = 1;
        atomicExch(&g_anyfb, 1);
    }
}

// ---------------- K5: s_all completion for fallback (flag-gated, rare) ----------------
__global__ __launch_bounds__(256) void k_sall_fb(
    const float* __restrict__ cls, const float* __restrict__ obj,
    const int* __restrict__ pbatch)
{
    if (!g_anyfb) return;
    int a = blockIdx.x * blockDim.x + threadIdx.x;
    if (a >= A_N || g_isc[a]) return;
    long long b = (long long)(*pbatch);
    float Bo = 1.f + __expf(-obj[b * A_N + a]);
    const float4* __restrict__ base = (const float4*)(cls + ((long long)b * A_N + a) * C_N);
    float q0 = sall_quarter(base, Bo);
    float q1 = sall_quarter(base + 5, Bo);
    float q2 = sall_quarter(base + 10, Bo);
    float q3 = sall_quarter(base + 15, Bo);
    g_sall[a] = f_add(f_add(f_add(q0, q1), q2), q3);
}

// ---------------- K6: fallback scan (8-way split, extremely rare) ----------------
__global__ __launch_bounds__(128) void k_fallback(
    const float* __restrict__ gt, const int* __restrict__ gtc,
    const float4* __restrict__ pb,
    const float* __restrict__ cls, const float* __restrict__ obj,
    const int* __restrict__ pbatch)
{
    int g = blockIdx.x >> 3, s = blockIdx.x & 7;
    if (!g_fb[g]) return;
    __shared__ GTBox sgt; __shared__ int scls;
    __shared__ unsigned long long sK[1280];
    if (threadIdx.x == 0) { sgt = make_gt(gt, g); scls = gtc[g]; }
    __syncthreads();
    GTBox B = sgt;
    long long b = (long long)(*pbatch);
    unsigned long long lk[10];
#pragma unroll
    for (int k = 0; k < 10; k++) lk[k] = 0xFFFFFFFFFFFFFFFFULL;
    int a0 = s * (A_N / 8);
    for (int a = a0 + threadIdx.x; a < a0 + A_N / 8; a += 128) {
        float4 p = pb[a];
        bool fg = g_fg[a] != 0;
        float iou = masked_iou(B, p, fg);
        float cx, cy, r;
        anchor_geom(a, cx, cy, r);
        bool cand = is_cand(B, cx, cy, r);
        float lg = logf(f_add(iou, 1e-8f));
        float tv = t_exact(cls[((long long)b * A_N + a) * C_N + scls], obj[b * A_N + a]);
        float cl = -f_add(tv, g_sall[a]);
        float c = f_sub(cl, f_mul(3.0f, lg));
        if (!cand) c = f_add(c, 100000.0f);
        if (!fg)   c = f_add(c, 1000000.0f);
        unsigned long long key = cost_key(c, a);
        if (key < lk[9]) {
#pragma unroll
            for (int k = 0; k < 10; k++)
                if (key < lk[k]) { unsigned long long t2 = lk[k]; lk[k] = key; key = t2; }
        }
    }
    int t = threadIdx.x;
#pragma unroll
    for (int k = 0; k < 10; k++) sK[t * 10 + k] = lk[k];
    for (int st = 64; st > 0; st >>= 1) {
        __syncthreads();
        if (t < st) {
            int b1 = t * 10, b2 = (t + st) * 10;
            unsigned long long mk[10]; int ii = 0, jj = 0;
#pragma unroll
            for (int k = 0; k < 10; k++) {
                unsigned long long v1 = sK[b1 + min(ii, 9)], v2 = sK[b2 + min(jj, 9)];
                bool t1 = (jj >= 10) || ((ii < 10) && (v1 <= v2));
                mk[k] = t1 ? v1 : v2;
                if (t1) ii++; else jj++;
            }
#pragma unroll
            for (int k = 0; k < 10; k++) sK[b1 + k] = mk[k];
        }
    }
    __syncthreads();
    if (t < 10) g_fkey[(g * 8 + s) * 10 + t] = sK[t];
}

// ---------------- K7: fallback merge + scatter ----------------
__global__ __launch_bounds__(128) void k_fbmerge(const float* __restrict__ gt,
                                                 const float4* __restrict__ pb)
{
    int g = blockIdx.x;
    if (!g_fb[g]) return;
    __shared__ unsigned long long sK[80];
    int t = threadIdx.x;
    if (t < 80) sK[t] = g_fkey[g * 80 + t];
    __syncthreads();
    if (t == 0) {
        GTBox B = make_gt(gt, g);
        int dk = g_dk[g];
        for (int k = 0; k < dk; k++) {
            int bi = 0; unsigned long long bv = 0xFFFFFFFFFFFFFFFFULL;
            for (int j = 0; j < 80; j++)
                if (sK[j] < bv) { bv = sK[j]; bi = j; }
            sK[bi] = 0xFFFFFFFFFFFFFFFFULL;
            int a = (int)(bv & 0xffffffffULL);
            atomicAdd(&g_cnt[a], 1);
            g_mgt[a] = g;
            g_miou[a] = masked_iou(B, pb[a], g_fg[a] != 0);
        }
    }
}

// ---------------- K8: finalize singles, collect multi ----------------
__global__ __launch_bounds__(256) void k_final(const int* __restrict__ gtc, float* __restrict__ out) {
    int a = blockIdx.x * blockDim.x + threadIdx.x;
    if (a >= A_N) return;
    int cnt = g_cnt[a];
    float cls = -1.f, fg = 0.f, iou = 0.f, ind = -1.f;
    if (cnt == 1) {
        int g = g_mgt[a];
        cls = (float)gtc[g]; fg = 1.f; iou = g_miou[a]; ind = (float)g;
        atomicAdd(&g_numfg, 1);
    } else if (cnt > 1) {
        fg = 1.f;
        atomicAdd(&g_numfg, 1);
        int m = atomicAdd(&g_mcnt, 1);
        g_multi[m] = a;
    }
    out[a] = cls;
    out[A_N + a] = fg;
    out[2 * A_N + a] = iou;
    out[3 * A_N + a] = ind;
}

// ---------------- K9: resolve multi-matched (warp per anchor) ----------------
__global__ __launch_bounds__(256) void k_multi(
    const float* __restrict__ gt, const int* __restrict__ gtc,
    const float4* __restrict__ pb, float* __restrict__ out,
    const float* __restrict__ cls, const float* __restrict__ obj,
    const int* __restrict__ pbatch)
{
    int w = (blockIdx.x * blockDim.x + threadIdx.x) >> 5;
    int lane = threadIdx.x & 31;
    int nw = (gridDim.x * blockDim.x) >> 5;
    if (w == 0 && lane == 0) out[4 * A_N] = (float)g_numfg;
    int M = g_mcnt;
    long long b = (long long)(*pbatch);
    for (int e = w; e < M; e += nw) {
        int a = g_multi[e];
        float4 p = pb[a];
        bool fg = g_fg[a] != 0;
        float cx, cy, r;
        anchor_geom(a, cx, cy, r);
        float sall = g_sall[a];
        float o = obj[b * A_N + a];
        float best = -FINF; int bg = 0x7fffffff;
        for (int g = lane; g < G_N; g += 32) {
            GTBox B = make_gt(gt, g);
            float iou = masked_iou(B, p, fg);
            bool cand = is_cand(B, cx, cy, r);
            float lg = logf(f_add(iou, 1e-8f));
            float tv = t_exact(cls[((long long)b * A_N + a) * C_N + gtc[g]], o);
            float cl = -f_add(tv, sall);
            float c = f_sub(cl, f_mul(3.0f, lg));
            if (!cand) c = f_add(c, 100000.0f);
            if (!fg)   c = f_add(c, 1000000.0f);
            if (c > best || (c == best && g < bg)) { best = c; bg = g; }
        }
#pragma unroll
        for (int o2 = 16; o2; o2 >>= 1) {
            float oc = __shfl_down_sync(0xffffffffu, best, o2);
            int og = __shfl_down_sync(0xffffffffu, bg, o2);
            if (oc > best || (oc == best && og < bg)) { best = oc; bg = og; }
        }
        bg = __shfl_sync(0xffffffffu, bg, 0);
        if (lane == 0) {
            GTBox B = make_gt(gt, bg);
            float iou = masked_iou(B, p, fg);
            out[a] = (float)gtc[bg];
            out[2 * A_N + a] = iou;
            out[3 * A_N + a] = (float)bg;
        }
    }
}

// ---------------- launch ----------------
extern "C" void kernel_launch(void* const* d_in, const int* in_sizes, int n_in,
                              void* d_out, int out_size) {
    const int*   batch = (const int*)d_in[0];
    const float* gt    = (const float*)d_in[3];
    const int*   gtc   = (const int*)d_in[4];
    const float* pb    = (const float*)d_in[5];
    const float* cp    = (const float*)d_in[9];
    const float* op    = (const float*)d_in[10];
    float* out = (float*)d_out;

    k_zero<<<(A_N + 255) / 256, 256>>>();
    k_fgmark<<<G_N, 128>>>(gt);
    k_sall_cand<<<(A_N * 4 + 255) / 256, 256>>>(cp, op, batch);
    k_bounds<<<(A_N + 255) / 256, 256>>>((const float4*)pb);
    k_assign<<<G_N, 256>>>(gt, gtc, (const float4*)pb, cp, op, batch);
    k_sall_fb<<<(A_N + 255) / 256, 256>>>(cp, op, batch);
    k_fallback<<<G_N * 8, 128>>>(gt, gtc, (const float4*)pb, cp, op, batch);
    k_fbmerge<<<G_N, 128>>>(gt, (const float4*)pb);
    k_final<<<(A_N + 255) / 256, 256>>>(gtc, out);
    k_multi<<<64, 256>>>(gt, gtc, (const float4*)pb, out, cp, op, batch);
}